// round 14
// baseline (speedup 1.0000x reference)
#include <cuda_runtime.h>

// ---------------------------------------------------------------------------
// SSIM fused single-kernel. Tile 32x64 outputs/block, 384 threads, 3 CTAs/SM.
// 4-channel reduction: blur (a,b) and (a^2+b^2, a*b) as packed f32x2 streams.
//   P1: SOFTWARE-PIPELINED stage of AB plane: all 28 LDGs front-batched into
//       registers (one DRAM latency exposure), then all STS.
//   P2: horizontal 11-tap conv, packed scatter (8 outputs/task) ->
//       two ull planes Hm=(mu1,mu2), Hq=(Q,P), [col][row] stride 75
//   P3: vertical 11-tap conv, register sliding window, pass-split + SSIM
// ---------------------------------------------------------------------------

typedef unsigned long long ull;

#define IMG      512
#define TW       32
#define TH       64
#define HALO     5
#define ROWS     74                // TH + 2*HALO
#define ABROW    46                // AB plane row stride (float2 units)
#define ABFLOATS (ROWS * ABROW * 2)          // 6808 floats = 27,232 B
#define NTHREADS 384
#define NWARPS   12
#define NBLOCKS  (16 * 8 * 64)     // 8192

#define HCOL     75                // H column stride in ull units (11*l mod 16 CF)
#define HPLANE   (32 * HCOL)       // 2400 ull = 19,200 B per plane
#define SMEM_BYTES (ABFLOATS * 4 + 2 * HPLANE * 8)   // 65,632 B

#define SSIM_C1 0.0001f
#define SSIM_C2 0.0009f

// packed tap weights in constant memory (uniform regs, no GPR cost)
__constant__ float2 cW2[6] = {
    { 1.0283735e-03f, 1.0283735e-03f },
    { 7.5987582e-03f, 7.5987582e-03f },
    { 3.6000773e-02f, 3.6000773e-02f },
    { 1.0936068e-01f, 1.0936068e-01f },
    { 2.1300554e-01f, 2.1300554e-01f },
    { 2.6601174e-01f, 2.6601174e-01f },
};
__device__ __forceinline__ ull wpk(int ks) {
    return *reinterpret_cast<const ull*>(&cW2[ks]);
}

// packed f32x2 helpers
__device__ __forceinline__ ull pk2(float lo, float hi) {
    ull d; asm("mov.b64 %0, {%1, %2};" : "=l"(d) : "f"(lo), "f"(hi)); return d;
}
__device__ __forceinline__ void unpk2(ull v, float& lo, float& hi) {
    asm("mov.b64 {%0, %1}, %2;" : "=f"(lo), "=f"(hi) : "l"(v));
}
__device__ __forceinline__ ull fma2(ull a, ull b, ull c) {
    ull d; asm("fma.rn.f32x2 %0, %1, %2, %3;" : "=l"(d) : "l"(a), "l"(b), "l"(c)); return d;
}
__device__ __forceinline__ ull mul2(ull a, ull b) {
    ull d; asm("mul.rn.f32x2 %0, %1, %2;" : "=l"(d) : "l"(a), "l"(b)); return d;
}
// packed symmetric 11-tap conv over window y at offset c (compile-time)
__device__ __forceinline__ ull conv11p(const ull* y, int c) {
    ull a = mul2(wpk(0), y[c + 0]);
    a = fma2(wpk(1), y[c + 1], a);
    a = fma2(wpk(2), y[c + 2], a);
    a = fma2(wpk(3), y[c + 3], a);
    a = fma2(wpk(4), y[c + 4], a);
    a = fma2(wpk(5), y[c + 5], a);
    a = fma2(wpk(4), y[c + 6], a);
    a = fma2(wpk(3), y[c + 7], a);
    a = fma2(wpk(2), y[c + 8], a);
    a = fma2(wpk(1), y[c + 9], a);
    a = fma2(wpk(0), y[c + 10], a);
    return a;
}

static __device__ double   g_acc = 0.0;
static __device__ unsigned g_cnt = 0u;

// P3 group: N outputs from one window; pass A (Hm) then pass B (Hq) reusing regs
template<int N>
__device__ __forceinline__ float p3_group(const ull* __restrict__ sHm,
                                          const ull* __restrict__ sHq,
                                          int base) {
    ull y[N + 10];
#pragma unroll
    for (int i = 0; i < N + 10; i++) y[i] = sHm[base + i];
    ull m[N];
#pragma unroll
    for (int i = 0; i < N; i++) m[i] = conv11p(y, i);
#pragma unroll
    for (int i = 0; i < N + 10; i++) y[i] = sHq[base + i];
    float s = 0.0f;
#pragma unroll
    for (int i = 0; i < N; i++) {
        const ull qp = conv11p(y, i);
        float m1, m2, Q, P;
        unpk2(m[i], m1, m2);
        unpk2(qp, Q, P);
        const float m1s  = m1 * m1;
        const float m2s  = m2 * m2;
        const float m12  = m1 * m2;
        const float s12  = P - m12;            // sigma12
        const float ssum = Q - m1s - m2s;      // sigma1^2 + sigma2^2
        const float num = (2.0f * m12 + SSIM_C1) * (2.0f * s12 + SSIM_C2);
        const float den = (m1s + m2s + SSIM_C1) * (ssum + SSIM_C2);
        s += __fdividef(num, den);
    }
    return s;
}

__global__ __launch_bounds__(NTHREADS, 3)
void ssim_kernel(const float* __restrict__ img1, const float* __restrict__ img2,
                 float* __restrict__ out) {
    extern __shared__ float sm[];
    float2* sAB = reinterpret_cast<float2*>(sm);                 // [74][46]
    ull*    sHm = reinterpret_cast<ull*>(sm + ABFLOATS);         // [32][75]
    ull*    sHq = sHm + HPLANE;                                  // [32][75]
    __shared__ float red[NWARPS];

    const int t    = threadIdx.x;
    const int lane = t & 31;
    const int wid  = t >> 5;        // 0..11
    const int gx0  = blockIdx.x * TW - HALO;
    const int gy0  = blockIdx.y * TH - HALO;
    const float* base1 = img1 + (size_t)blockIdx.z * (IMG * IMG);
    const float* base2 = img2 + (size_t)blockIdx.z * (IMG * IMG);

    // ---- Phase 1: software-pipelined stage of AB (zero-padded) ----
    // Pass 1: issue ALL predicated LDGs front-batched into registers (MLP~28).
    // Pass 2: all STS. One DRAM latency exposure instead of ~6.
    {
        float a0[7], b0[7], a1[7], b1[7];
        const int gxA = gx0 + lane;
        const int gxB = gx0 + lane + 32;
        const bool okA0 = (unsigned)gxA < (unsigned)IMG;
        const bool okB0 = (lane < 10) && ((unsigned)gxB < (unsigned)IMG);
#pragma unroll
        for (int i = 0; i < 7; i++) {
            const int r  = wid + i * NWARPS;
            const int gy = gy0 + r;
            const bool yok = (r < ROWS) && ((unsigned)gy < (unsigned)IMG);
            const bool okA = yok && okA0;
            const bool okB = yok && okB0;
            const int oA = gy * IMG + gxA;
            const int oB = gy * IMG + gxB;
            a0[i] = okA ? base1[oA] : 0.0f;
            b0[i] = okA ? base2[oA] : 0.0f;
            a1[i] = okB ? base1[oB] : 0.0f;
            b1[i] = okB ? base2[oB] : 0.0f;
        }
#pragma unroll
        for (int i = 0; i < 7; i++) {
            const int r = wid + i * NWARPS;
            if (r < ROWS) {
                sAB[r * ABROW + lane] = make_float2(a0[i], b0[i]);
                if (lane < 10)
                    sAB[r * ABROW + lane + 32] = make_float2(a1[i], b1[i]);
            }
        }
    }
    __syncthreads();

    // ---- Phase 2: horizontal conv, packed scatter, 8 outputs per task ----
    // 296 tasks = 4 col-groups x 74 rows.
    if (t < 4 * ROWS) {
        const int g = t / ROWS;          // 0..3
        const int r = t - g * ROWS;      // 0..73
        const float2* abrow = sAB + r * ABROW + g * 8;

        ull mAB[8] = {0,0,0,0,0,0,0,0};
        ull mQP[8] = {0,0,0,0,0,0,0,0};

        // stream 18 window elements as 9x LDS.128 (2 packed pairs each)
#pragma unroll
        for (int blk = 0; blk < 9; blk++) {
            const ulonglong2 v = *reinterpret_cast<const ulonglong2*>(
                abrow + 2 * blk);
#pragma unroll
            for (int sub = 0; sub < 2; sub++) {
                const int e = 2 * blk + sub;      // 0..17, compile-time
                const ull ab = sub ? v.y : v.x;
                float a, b;
                unpk2(ab, a, b);
                const float q = fmaf(a, a, b * b);    // a^2 + b^2
                const float p = a * b;
                const ull qp = pk2(q, p);
#pragma unroll
                for (int j = 0; j < 8; j++) {
                    const int k = e - j;              // compile-time
                    if (k >= 0 && k < 11) {
                        const int ks = (k < 6) ? k : 10 - k;
                        mAB[j] = fma2(wpk(ks), ab, mAB[j]);
                        mQP[j] = fma2(wpk(ks), qp, mQP[j]);
                    }
                }
            }
        }
        // ST.64 into transposed H planes (phase banks: r mod 16, conflict-free)
#pragma unroll
        for (int j = 0; j < 8; j++) {
            const int c = g * 8 + j;
            sHm[c * HCOL + r] = mAB[j];
            sHq[c * HCOL + r] = mQP[j];
        }
    }
    __syncthreads();

    // ---- Phase 3: vertical conv, register sliding window, pass-split ----
    float lsum = 0.0f;
    {
        const int col = lane;
        if (wid < 8) {                    // 6 rows: two groups of 3
            const int r0 = 6 * wid;
            const int base = col * HCOL + r0;
            lsum += p3_group<3>(sHm, sHq, base);
            lsum += p3_group<3>(sHm, sHq, base + 3);
        } else {                          // 4 rows: two groups of 2
            const int r0 = 48 + 4 * (wid - 8);
            const int base = col * HCOL + r0;
            lsum += p3_group<2>(sHm, sHq, base);
            lsum += p3_group<2>(sHm, sHq, base + 2);
        }
    }

    // ---- warp reduce -> block reduce -> one global atomic per block ----
#pragma unroll
    for (int off = 16; off > 0; off >>= 1)
        lsum += __shfl_xor_sync(0xffffffffu, lsum, off);
    if (lane == 0) red[wid] = lsum;
    __syncthreads();
    if (t == 0) {
        float s = 0.0f;
#pragma unroll
        for (int i = 0; i < NWARPS; i++) s += red[i];
        atomicAdd(&g_acc, (double)s);
        __threadfence();
        const unsigned old = atomicAdd(&g_cnt, 1u);
        if (old == NBLOCKS - 1) {
            const ull raw = atomicExch(reinterpret_cast<ull*>(&g_acc), 0ull);
            out[0] = (float)(__longlong_as_double(raw) * (1.0 / 16777216.0));
            g_cnt = 0u;
        }
    }
}

extern "C" void kernel_launch(void* const* d_in, const int* in_sizes, int n_in,
                              void* d_out, int out_size) {
    const float* img1 = (const float*)d_in[0];
    const float* img2 = (const float*)d_in[1];
    float* out = (float*)d_out;

    cudaFuncSetAttribute(ssim_kernel,
                         cudaFuncAttributeMaxDynamicSharedMemorySize, SMEM_BYTES);

    dim3 grid(IMG / TW, IMG / TH, 64);   // 16 x 8 x 64 = 8192 blocks
    ssim_kernel<<<grid, NTHREADS, SMEM_BYTES>>>(img1, img2, out);
}

// round 15
// speedup vs baseline: 1.3544x; 1.3544x over previous
#include <cuda_runtime.h>

// ---------------------------------------------------------------------------
// SSIM fused single-kernel. Tile 32x64 outputs/block, 384 threads, 4 CTAs/SM.
// 4-channel reduction: blur (a,b) and (a^2+b^2, a*b) as packed f32x2 streams.
//   P1: software-pipelined stage of AB plane (28 LDGs front-batched)
//   2 vertical chunks (h-rows 0..41 / 32..73), H holds 42 rows only:
//     P2: horizontal conv, packed scatter, 4 outputs/task (336 tasks) ->
//         Hm=(mu1,mu2), Hq=(Q,P) ull planes [col][row] stride 43
//     P3: vertical conv, N=2 register-window groups, pass-split + SSIM
// smem 49,248 B -> 4 CTAs/SM (reg cap 42: P2 16 accums, P3 y[12] windows)
// ---------------------------------------------------------------------------

typedef unsigned long long ull;

#define IMG      512
#define TW       32
#define TH       64
#define HALO     5
#define ROWS     74                // TH + 2*HALO
#define ABROW    46                // AB plane row stride (float2 units)
#define ABFLOATS (ROWS * ABROW * 2)          // 6808 floats = 27,232 B
#define NTHREADS 384
#define NWARPS   12
#define NBLOCKS  (16 * 8 * 64)     // 8192

#define CH_ROWS  42                // h-conv rows per chunk (32 outputs + 10)
#define HCOL     43                // H column stride in ull (11c mod 16 -> CF)
#define HPLANE   (32 * HCOL)       // 1376 ull = 11,008 B per plane
#define SMEM_BYTES (ABFLOATS * 4 + 2 * HPLANE * 8)   // 49,248 B

#define SSIM_C1 0.0001f
#define SSIM_C2 0.0009f

// packed tap weights in constant memory (uniform regs, no GPR cost)
__constant__ float2 cW2[6] = {
    { 1.0283735e-03f, 1.0283735e-03f },
    { 7.5987582e-03f, 7.5987582e-03f },
    { 3.6000773e-02f, 3.6000773e-02f },
    { 1.0936068e-01f, 1.0936068e-01f },
    { 2.1300554e-01f, 2.1300554e-01f },
    { 2.6601174e-01f, 2.6601174e-01f },
};
__device__ __forceinline__ ull wpk(int ks) {
    return *reinterpret_cast<const ull*>(&cW2[ks]);
}

// packed f32x2 helpers
__device__ __forceinline__ ull pk2(float lo, float hi) {
    ull d; asm("mov.b64 %0, {%1, %2};" : "=l"(d) : "f"(lo), "f"(hi)); return d;
}
__device__ __forceinline__ void unpk2(ull v, float& lo, float& hi) {
    asm("mov.b64 {%0, %1}, %2;" : "=f"(lo), "=f"(hi) : "l"(v));
}
__device__ __forceinline__ ull fma2(ull a, ull b, ull c) {
    ull d; asm("fma.rn.f32x2 %0, %1, %2, %3;" : "=l"(d) : "l"(a), "l"(b), "l"(c)); return d;
}
__device__ __forceinline__ ull mul2(ull a, ull b) {
    ull d; asm("mul.rn.f32x2 %0, %1, %2;" : "=l"(d) : "l"(a), "l"(b)); return d;
}
// packed symmetric 11-tap conv over window y at offset c (compile-time)
__device__ __forceinline__ ull conv11p(const ull* y, int c) {
    ull a = mul2(wpk(0), y[c + 0]);
    a = fma2(wpk(1), y[c + 1], a);
    a = fma2(wpk(2), y[c + 2], a);
    a = fma2(wpk(3), y[c + 3], a);
    a = fma2(wpk(4), y[c + 4], a);
    a = fma2(wpk(5), y[c + 5], a);
    a = fma2(wpk(4), y[c + 6], a);
    a = fma2(wpk(3), y[c + 7], a);
    a = fma2(wpk(2), y[c + 8], a);
    a = fma2(wpk(1), y[c + 9], a);
    a = fma2(wpk(0), y[c + 10], a);
    return a;
}

static __device__ double   g_acc = 0.0;
static __device__ unsigned g_cnt = 0u;

// P3 group: 2 outputs; pass A (Hm) then pass B (Hq) reusing window regs
__device__ __forceinline__ float p3_group2(const ull* __restrict__ sHm,
                                           const ull* __restrict__ sHq,
                                           int base) {
    ull y[12];
#pragma unroll
    for (int i = 0; i < 12; i++) y[i] = sHm[base + i];
    ull m0 = conv11p(y, 0);
    ull m1v = conv11p(y, 1);
#pragma unroll
    for (int i = 0; i < 12; i++) y[i] = sHq[base + i];
    float s = 0.0f;
#pragma unroll
    for (int i = 0; i < 2; i++) {
        const ull qp = conv11p(y, i);
        float m1, m2, Q, P;
        unpk2(i == 0 ? m0 : m1v, m1, m2);
        unpk2(qp, Q, P);
        const float m1s  = m1 * m1;
        const float m2s  = m2 * m2;
        const float m12  = m1 * m2;
        const float s12  = P - m12;            // sigma12
        const float ssum = Q - m1s - m2s;      // sigma1^2 + sigma2^2
        const float num = (2.0f * m12 + SSIM_C1) * (2.0f * s12 + SSIM_C2);
        const float den = (m1s + m2s + SSIM_C1) * (ssum + SSIM_C2);
        s += __fdividef(num, den);
    }
    return s;
}

__global__ __launch_bounds__(NTHREADS, 4)
void ssim_kernel(const float* __restrict__ img1, const float* __restrict__ img2,
                 float* __restrict__ out) {
    extern __shared__ float sm[];
    float2* sAB = reinterpret_cast<float2*>(sm);                 // [74][46]
    ull*    sHm = reinterpret_cast<ull*>(sm + ABFLOATS);         // [32][43]
    ull*    sHq = sHm + HPLANE;                                  // [32][43]
    __shared__ float red[NWARPS];

    const int t    = threadIdx.x;
    const int lane = t & 31;
    const int wid  = t >> 5;        // 0..11
    const int gx0  = blockIdx.x * TW - HALO;
    const int gy0  = blockIdx.y * TH - HALO;
    const float* base1 = img1 + (size_t)blockIdx.z * (IMG * IMG);
    const float* base2 = img2 + (size_t)blockIdx.z * (IMG * IMG);

    // ---- Phase 1: software-pipelined stage of AB (zero-padded) ----
    {
        float a0[7], b0[7], a1[7], b1[7];
        const int gxA = gx0 + lane;
        const int gxB = gx0 + lane + 32;
        const bool okA0 = (unsigned)gxA < (unsigned)IMG;
        const bool okB0 = (lane < 10) && ((unsigned)gxB < (unsigned)IMG);
#pragma unroll
        for (int i = 0; i < 7; i++) {
            const int r  = wid + i * NWARPS;
            const int gy = gy0 + r;
            const bool yok = (r < ROWS) && ((unsigned)gy < (unsigned)IMG);
            const bool okA = yok && okA0;
            const bool okB = yok && okB0;
            const int oA = gy * IMG + gxA;
            const int oB = gy * IMG + gxB;
            a0[i] = okA ? base1[oA] : 0.0f;
            b0[i] = okA ? base2[oA] : 0.0f;
            a1[i] = okB ? base1[oB] : 0.0f;
            b1[i] = okB ? base2[oB] : 0.0f;
        }
#pragma unroll
        for (int i = 0; i < 7; i++) {
            const int r = wid + i * NWARPS;
            if (r < ROWS) {
                sAB[r * ABROW + lane] = make_float2(a0[i], b0[i]);
                if (lane < 10)
                    sAB[r * ABROW + lane + 32] = make_float2(a1[i], b1[i]);
            }
        }
    }
    __syncthreads();

    float lsum = 0.0f;

#pragma unroll
    for (int chunk = 0; chunk < 2; chunk++) {
        const int rowbase = chunk * 32;      // AB row offset for this chunk

        // ---- Phase 2: horizontal conv, packed scatter, 4 outputs/task ----
        // 336 tasks = 8 col-groups x 42 rows.
        if (t < 8 * CH_ROWS) {
            const int g = t / CH_ROWS;       // 0..7
            const int r = t - g * CH_ROWS;   // 0..41
            const float2* abrow = sAB + (rowbase + r) * ABROW + g * 4;

            ull mAB[4] = {0ull, 0ull, 0ull, 0ull};
            ull mQP[4] = {0ull, 0ull, 0ull, 0ull};

            // stream 14 window elements as 7x LDS.128 (2 packed pairs each)
#pragma unroll
            for (int blk = 0; blk < 7; blk++) {
                const ulonglong2 v = *reinterpret_cast<const ulonglong2*>(
                    abrow + 2 * blk);
#pragma unroll
                for (int sub = 0; sub < 2; sub++) {
                    const int e = 2 * blk + sub;      // 0..13, compile-time
                    const ull ab = sub ? v.y : v.x;
                    float a, b;
                    unpk2(ab, a, b);
                    const float q = fmaf(a, a, b * b);    // a^2 + b^2
                    const float p = a * b;
                    const ull qp = pk2(q, p);
#pragma unroll
                    for (int j = 0; j < 4; j++) {
                        const int k = e - j;              // compile-time
                        if (k >= 0 && k < 11) {
                            const int ks = (k < 6) ? k : 10 - k;
                            mAB[j] = fma2(wpk(ks), ab, mAB[j]);
                            mQP[j] = fma2(wpk(ks), qp, mQP[j]);
                        }
                    }
                }
            }
#pragma unroll
            for (int j = 0; j < 4; j++) {
                const int c = g * 4 + j;
                sHm[c * HCOL + r] = mAB[j];
                sHq[c * HCOL + r] = mQP[j];
            }
        }
        __syncthreads();

        // ---- Phase 3: vertical conv, N=2 register-window groups ----
        {
            const int col = lane;
            if (wid < 4) {                    // rows 4w..4w+3: two groups
                const int base = col * HCOL + 4 * wid;
                lsum += p3_group2(sHm, sHq, base);
                lsum += p3_group2(sHm, sHq, base + 2);
            } else {                          // rows 16+2(w-4): one group
                const int base = col * HCOL + 16 + 2 * (wid - 4);
                lsum += p3_group2(sHm, sHq, base);
            }
        }
        __syncthreads();
    }

    // ---- warp reduce -> block reduce -> one global atomic per block ----
#pragma unroll
    for (int off = 16; off > 0; off >>= 1)
        lsum += __shfl_xor_sync(0xffffffffu, lsum, off);
    if (lane == 0) red[wid] = lsum;
    __syncthreads();
    if (t == 0) {
        float s = 0.0f;
#pragma unroll
        for (int i = 0; i < NWARPS; i++) s += red[i];
        atomicAdd(&g_acc, (double)s);
        __threadfence();
        const unsigned old = atomicAdd(&g_cnt, 1u);
        if (old == NBLOCKS - 1) {
            const ull raw = atomicExch(reinterpret_cast<ull*>(&g_acc), 0ull);
            out[0] = (float)(__longlong_as_double(raw) * (1.0 / 16777216.0));
            g_cnt = 0u;
        }
    }
}

extern "C" void kernel_launch(void* const* d_in, const int* in_sizes, int n_in,
                              void* d_out, int out_size) {
    const float* img1 = (const float*)d_in[0];
    const float* img2 = (const float*)d_in[1];
    float* out = (float*)d_out;

    cudaFuncSetAttribute(ssim_kernel,
                         cudaFuncAttributeMaxDynamicSharedMemorySize, SMEM_BYTES);

    dim3 grid(IMG / TW, IMG / TH, 64);   // 16 x 8 x 64 = 8192 blocks
    ssim_kernel<<<grid, NTHREADS, SMEM_BYTES>>>(img1, img2, out);
}

// round 16
// speedup vs baseline: 1.5328x; 1.1317x over previous
#include <cuda_runtime.h>

// ---------------------------------------------------------------------------
// SSIM fused single-kernel. Tile 32x64 outputs/block, 384 threads, 4 CTAs/SM.
// 4-channel reduction: blur (a,b) and (a^2+b^2, a*b) as packed f32x2 streams.
//   P1: software-pipelined stage of AB plane (28 LDGs front-batched)
//   2 vertical chunks (h-rows 0..41 / 32..73), H holds 42 rows only:
//     P2: horizontal conv, packed scatter, 4 outputs/task (336 tasks) ->
//         Hm=(mu1,mu2), Hq=(Q,P) ull planes [col][row] stride 43
//     P3: vertical conv, N=4 outputs per thread via ROTATING 11-reg ring
//         (two passes: Hm then Hq reusing ring regs) + SSIM
// smem 49,248 B -> 4 CTAs/SM; ring keeps peak regs within the 42 cap.
// ---------------------------------------------------------------------------

typedef unsigned long long ull;

#define IMG      512
#define TW       32
#define TH       64
#define HALO     5
#define ROWS     74                // TH + 2*HALO
#define ABROW    46                // AB plane row stride (float2 units)
#define ABFLOATS (ROWS * ABROW * 2)          // 6808 floats = 27,232 B
#define NTHREADS 384
#define NWARPS   12
#define NBLOCKS  (16 * 8 * 64)     // 8192

#define CH_ROWS  42                // h-conv rows per chunk (32 outputs + 10)
#define HCOL     43                // H column stride in ull (11c mod 16 -> CF)
#define HPLANE   (32 * HCOL)       // 1376 ull = 11,008 B per plane
#define SMEM_BYTES (ABFLOATS * 4 + 2 * HPLANE * 8)   // 49,248 B

#define SSIM_C1 0.0001f
#define SSIM_C2 0.0009f

// packed tap weights in constant memory (uniform regs, no GPR cost)
__constant__ float2 cW2[6] = {
    { 1.0283735e-03f, 1.0283735e-03f },
    { 7.5987582e-03f, 7.5987582e-03f },
    { 3.6000773e-02f, 3.6000773e-02f },
    { 1.0936068e-01f, 1.0936068e-01f },
    { 2.1300554e-01f, 2.1300554e-01f },
    { 2.6601174e-01f, 2.6601174e-01f },
};
__device__ __forceinline__ ull wpk(int ks) {
    return *reinterpret_cast<const ull*>(&cW2[ks]);
}

// packed f32x2 helpers
__device__ __forceinline__ ull pk2(float lo, float hi) {
    ull d; asm("mov.b64 %0, {%1, %2};" : "=l"(d) : "f"(lo), "f"(hi)); return d;
}
__device__ __forceinline__ void unpk2(ull v, float& lo, float& hi) {
    asm("mov.b64 {%0, %1}, %2;" : "=f"(lo), "=f"(hi) : "l"(v));
}
__device__ __forceinline__ ull fma2(ull a, ull b, ull c) {
    ull d; asm("fma.rn.f32x2 %0, %1, %2, %3;" : "=l"(d) : "l"(a), "l"(b), "l"(c)); return d;
}
__device__ __forceinline__ ull mul2(ull a, ull b) {
    ull d; asm("mul.rn.f32x2 %0, %1, %2;" : "=l"(d) : "l"(a), "l"(b)); return d;
}

// packed symmetric 11-tap conv over an 11-register RING at rotation rot
// (rot is compile-time under full unroll -> static indices, pure renaming)
__device__ __forceinline__ ull conv11r(const ull* y, int rot) {
    ull a = mul2(wpk(0), y[rot % 11]);
#pragma unroll
    for (int k = 1; k < 11; k++) {
        const int ks = (k < 6) ? k : 10 - k;
        a = fma2(wpk(ks), y[(rot + k) % 11], a);
    }
    return a;
}

static __device__ double   g_acc = 0.0;
static __device__ unsigned g_cnt = 0u;

// P3: 4 outputs from one column; pass A (Hm) fills ring + slides, then
// pass B (Hq) reuses the same ring registers; epilogue consumes m[] in order.
__device__ __forceinline__ float p3_group4(const ull* __restrict__ sHm,
                                           const ull* __restrict__ sHq,
                                           int base) {
    ull y[11];
    ull m[4];

    // pass A: (mu1, mu2)
#pragma unroll
    for (int i = 0; i < 11; i++) y[i] = sHm[base + i];
    m[0] = conv11r(y, 0);
#pragma unroll
    for (int i = 1; i < 4; i++) {
        y[(i - 1) % 11] = sHm[base + 10 + i];
        m[i] = conv11r(y, i);
    }

    // pass B: (Q, P) + SSIM epilogue
    float s = 0.0f;
#pragma unroll
    for (int i = 0; i < 11; i++) y[i] = sHq[base + i];
#pragma unroll
    for (int i = 0; i < 4; i++) {
        if (i > 0) y[(i - 1) % 11] = sHq[base + 10 + i];
        const ull qp = conv11r(y, i);
        float m1, m2, Q, P;
        unpk2(m[i], m1, m2);
        unpk2(qp, Q, P);
        const float m1s  = m1 * m1;
        const float m2s  = m2 * m2;
        const float m12  = m1 * m2;
        const float s12  = P - m12;            // sigma12
        const float ssum = Q - m1s - m2s;      // sigma1^2 + sigma2^2
        const float num = (2.0f * m12 + SSIM_C1) * (2.0f * s12 + SSIM_C2);
        const float den = (m1s + m2s + SSIM_C1) * (ssum + SSIM_C2);
        s += __fdividef(num, den);
    }
    return s;
}

__global__ __launch_bounds__(NTHREADS, 4)
void ssim_kernel(const float* __restrict__ img1, const float* __restrict__ img2,
                 float* __restrict__ out) {
    extern __shared__ float sm[];
    float2* sAB = reinterpret_cast<float2*>(sm);                 // [74][46]
    ull*    sHm = reinterpret_cast<ull*>(sm + ABFLOATS);         // [32][43]
    ull*    sHq = sHm + HPLANE;                                  // [32][43]
    __shared__ float red[NWARPS];

    const int t    = threadIdx.x;
    const int lane = t & 31;
    const int wid  = t >> 5;        // 0..11
    const int gx0  = blockIdx.x * TW - HALO;
    const int gy0  = blockIdx.y * TH - HALO;
    const float* base1 = img1 + (size_t)blockIdx.z * (IMG * IMG);
    const float* base2 = img2 + (size_t)blockIdx.z * (IMG * IMG);

    // ---- Phase 1: software-pipelined stage of AB (zero-padded) ----
    {
        float a0[7], b0[7], a1[7], b1[7];
        const int gxA = gx0 + lane;
        const int gxB = gx0 + lane + 32;
        const bool okA0 = (unsigned)gxA < (unsigned)IMG;
        const bool okB0 = (lane < 10) && ((unsigned)gxB < (unsigned)IMG);
#pragma unroll
        for (int i = 0; i < 7; i++) {
            const int r  = wid + i * NWARPS;
            const int gy = gy0 + r;
            const bool yok = (r < ROWS) && ((unsigned)gy < (unsigned)IMG);
            const bool okA = yok && okA0;
            const bool okB = yok && okB0;
            const int oA = gy * IMG + gxA;
            const int oB = gy * IMG + gxB;
            a0[i] = okA ? base1[oA] : 0.0f;
            b0[i] = okA ? base2[oA] : 0.0f;
            a1[i] = okB ? base1[oB] : 0.0f;
            b1[i] = okB ? base2[oB] : 0.0f;
        }
#pragma unroll
        for (int i = 0; i < 7; i++) {
            const int r = wid + i * NWARPS;
            if (r < ROWS) {
                sAB[r * ABROW + lane] = make_float2(a0[i], b0[i]);
                if (lane < 10)
                    sAB[r * ABROW + lane + 32] = make_float2(a1[i], b1[i]);
            }
        }
    }
    __syncthreads();

    float lsum = 0.0f;

#pragma unroll
    for (int chunk = 0; chunk < 2; chunk++) {
        const int rowbase = chunk * 32;      // AB row offset for this chunk

        // ---- Phase 2: horizontal conv, packed scatter, 4 outputs/task ----
        // 336 tasks = 8 col-groups x 42 rows.
        if (t < 8 * CH_ROWS) {
            const int g = t / CH_ROWS;       // 0..7
            const int r = t - g * CH_ROWS;   // 0..41
            const float2* abrow = sAB + (rowbase + r) * ABROW + g * 4;

            ull mAB[4] = {0ull, 0ull, 0ull, 0ull};
            ull mQP[4] = {0ull, 0ull, 0ull, 0ull};

            // stream 14 window elements as 7x LDS.128 (2 packed pairs each)
#pragma unroll
            for (int blk = 0; blk < 7; blk++) {
                const ulonglong2 v = *reinterpret_cast<const ulonglong2*>(
                    abrow + 2 * blk);
#pragma unroll
                for (int sub = 0; sub < 2; sub++) {
                    const int e = 2 * blk + sub;      // 0..13, compile-time
                    const ull ab = sub ? v.y : v.x;
                    float a, b;
                    unpk2(ab, a, b);
                    const float q = fmaf(a, a, b * b);    // a^2 + b^2
                    const float p = a * b;
                    const ull qp = pk2(q, p);
#pragma unroll
                    for (int j = 0; j < 4; j++) {
                        const int k = e - j;              // compile-time
                        if (k >= 0 && k < 11) {
                            const int ks = (k < 6) ? k : 10 - k;
                            mAB[j] = fma2(wpk(ks), ab, mAB[j]);
                            mQP[j] = fma2(wpk(ks), qp, mQP[j]);
                        }
                    }
                }
            }
#pragma unroll
            for (int j = 0; j < 4; j++) {
                const int c = g * 4 + j;
                sHm[c * HCOL + r] = mAB[j];
                sHq[c * HCOL + r] = mQP[j];
            }
        }
        __syncthreads();

        // ---- Phase 3: vertical conv, N=4 ring groups (warps 0..7) ----
        if (wid < 8) {
            const int base = lane * HCOL + 4 * wid;   // rows 4w..4w+13 <= 41
            lsum += p3_group4(sHm, sHq, base);
        }
        __syncthreads();
    }

    // ---- warp reduce -> block reduce -> one global atomic per block ----
#pragma unroll
    for (int off = 16; off > 0; off >>= 1)
        lsum += __shfl_xor_sync(0xffffffffu, lsum, off);
    if (lane == 0) red[wid] = lsum;
    __syncthreads();
    if (t == 0) {
        float s = 0.0f;
#pragma unroll
        for (int i = 0; i < NWARPS; i++) s += red[i];
        atomicAdd(&g_acc, (double)s);
        __threadfence();
        const unsigned old = atomicAdd(&g_cnt, 1u);
        if (old == NBLOCKS - 1) {
            const ull raw = atomicExch(reinterpret_cast<ull*>(&g_acc), 0ull);
            out[0] = (float)(__longlong_as_double(raw) * (1.0 / 16777216.0));
            g_cnt = 0u;
        }
    }
}

extern "C" void kernel_launch(void* const* d_in, const int* in_sizes, int n_in,
                              void* d_out, int out_size) {
    const float* img1 = (const float*)d_in[0];
    const float* img2 = (const float*)d_in[1];
    float* out = (float*)d_out;

    cudaFuncSetAttribute(ssim_kernel,
                         cudaFuncAttributeMaxDynamicSharedMemorySize, SMEM_BYTES);

    dim3 grid(IMG / TW, IMG / TH, 64);   // 16 x 8 x 64 = 8192 blocks
    ssim_kernel<<<grid, NTHREADS, SMEM_BYTES>>>(img1, img2, out);
}

// round 17
// speedup vs baseline: 1.6291x; 1.0628x over previous
#include <cuda_runtime.h>

// ---------------------------------------------------------------------------
// SSIM fused single-kernel. Tile 32x64 outputs/block, 384 threads, 4 CTAs/SM.
// 4-channel reduction: blur (a,b) and (a^2+b^2, a*b) as packed f32x2 streams.
//   P1: software-pipelined stage of AB plane (28 LDGs front-batched)
//   chunk 1: P2 h-rows 0..41 (336 tasks) -> H[0..41]; P3 outputs 0..31
//   copy:    H rows 32..41 -> rows 0..9  (reuse, no recompute)
//   chunk 2: P2 h-rows 42..73 (256 tasks, shift-only addressing) -> H[10..41];
//            P3 outputs 32..63
//   P3: vertical conv, N=4 outputs, flat y[14] window via 7x LDS.128
// H planes stride 42 (even -> aligned .128; 21*lane mod 16 -> conflict-free)
// smem 48,736 B -> 4 CTAs/SM.
// ---------------------------------------------------------------------------

typedef unsigned long long ull;

#define IMG      512
#define TW       32
#define TH       64
#define HALO     5
#define ROWS     74                // TH + 2*HALO
#define ABROW    46                // AB plane row stride (float2 units)
#define ABFLOATS (ROWS * ABROW * 2)          // 6808 floats = 27,232 B
#define NTHREADS 384
#define NWARPS   12
#define NBLOCKS  (16 * 8 * 64)     // 8192

#define HCOL     42                // H column stride in ull (even, CF for .128)
#define HPLANE   (32 * HCOL)       // 1344 ull = 10,752 B per plane
#define SMEM_BYTES (ABFLOATS * 4 + 2 * HPLANE * 8)   // 48,736 B

#define SSIM_C1 0.0001f
#define SSIM_C2 0.0009f

// packed tap weights in constant memory (uniform regs, no GPR cost)
__constant__ float2 cW2[6] = {
    { 1.0283735e-03f, 1.0283735e-03f },
    { 7.5987582e-03f, 7.5987582e-03f },
    { 3.6000773e-02f, 3.6000773e-02f },
    { 1.0936068e-01f, 1.0936068e-01f },
    { 2.1300554e-01f, 2.1300554e-01f },
    { 2.6601174e-01f, 2.6601174e-01f },
};
__device__ __forceinline__ ull wpk(int ks) {
    return *reinterpret_cast<const ull*>(&cW2[ks]);
}

// packed f32x2 helpers
__device__ __forceinline__ ull pk2(float lo, float hi) {
    ull d; asm("mov.b64 %0, {%1, %2};" : "=l"(d) : "f"(lo), "f"(hi)); return d;
}
__device__ __forceinline__ void unpk2(ull v, float& lo, float& hi) {
    asm("mov.b64 {%0, %1}, %2;" : "=f"(lo), "=f"(hi) : "l"(v));
}
__device__ __forceinline__ ull fma2(ull a, ull b, ull c) {
    ull d; asm("fma.rn.f32x2 %0, %1, %2, %3;" : "=l"(d) : "l"(a), "l"(b), "l"(c)); return d;
}
__device__ __forceinline__ ull mul2(ull a, ull b) {
    ull d; asm("mul.rn.f32x2 %0, %1, %2;" : "=l"(d) : "l"(a), "l"(b)); return d;
}
// packed symmetric 11-tap conv over flat window y at offset c (compile-time)
__device__ __forceinline__ ull conv11p(const ull* y, int c) {
    ull a = mul2(wpk(0), y[c + 0]);
    a = fma2(wpk(1), y[c + 1], a);
    a = fma2(wpk(2), y[c + 2], a);
    a = fma2(wpk(3), y[c + 3], a);
    a = fma2(wpk(4), y[c + 4], a);
    a = fma2(wpk(5), y[c + 5], a);
    a = fma2(wpk(4), y[c + 6], a);
    a = fma2(wpk(3), y[c + 7], a);
    a = fma2(wpk(2), y[c + 8], a);
    a = fma2(wpk(1), y[c + 9], a);
    a = fma2(wpk(0), y[c + 10], a);
    return a;
}

static __device__ double   g_acc = 0.0;
static __device__ unsigned g_cnt = 0u;

// P3: 4 outputs from one column. Flat 14-row window via 7x LDS.128;
// pass A (Hm), then pass B (Hq) reusing window regs + SSIM epilogue.
__device__ __forceinline__ float p3_group4(const ull* __restrict__ sHm,
                                           const ull* __restrict__ sHq,
                                           int base) {
    ull y[14];
    ull m[4];

    const ulonglong2* pm = reinterpret_cast<const ulonglong2*>(sHm + base);
#pragma unroll
    for (int i = 0; i < 7; i++) {
        const ulonglong2 v = pm[i];
        y[2 * i]     = v.x;
        y[2 * i + 1] = v.y;
    }
#pragma unroll
    for (int i = 0; i < 4; i++) m[i] = conv11p(y, i);

    const ulonglong2* pq = reinterpret_cast<const ulonglong2*>(sHq + base);
#pragma unroll
    for (int i = 0; i < 7; i++) {
        const ulonglong2 v = pq[i];
        y[2 * i]     = v.x;
        y[2 * i + 1] = v.y;
    }
    float s = 0.0f;
#pragma unroll
    for (int i = 0; i < 4; i++) {
        const ull qp = conv11p(y, i);
        float m1, m2, Q, P;
        unpk2(m[i], m1, m2);
        unpk2(qp, Q, P);
        const float m1s  = m1 * m1;
        const float m2s  = m2 * m2;
        const float m12  = m1 * m2;
        const float s12  = P - m12;            // sigma12
        const float ssum = Q - m1s - m2s;      // sigma1^2 + sigma2^2
        const float num = (2.0f * m12 + SSIM_C1) * (2.0f * s12 + SSIM_C2);
        const float den = (m1s + m2s + SSIM_C1) * (ssum + SSIM_C2);
        s += __fdividef(num, den);
    }
    return s;
}

// P2 inner body: conv 14-element window -> 4 packed outputs at H row hr
__device__ __forceinline__ void p2_task(const float2* __restrict__ abrow,
                                        ull* __restrict__ sHm,
                                        ull* __restrict__ sHq,
                                        int cbase, int hr) {
    ull mAB[4] = {0ull, 0ull, 0ull, 0ull};
    ull mQP[4] = {0ull, 0ull, 0ull, 0ull};
#pragma unroll
    for (int blk = 0; blk < 7; blk++) {
        const ulonglong2 v = *reinterpret_cast<const ulonglong2*>(abrow + 2 * blk);
#pragma unroll
        for (int sub = 0; sub < 2; sub++) {
            const int e = 2 * blk + sub;      // 0..13, compile-time
            const ull ab = sub ? v.y : v.x;
            float a, b;
            unpk2(ab, a, b);
            const float q = fmaf(a, a, b * b);    // a^2 + b^2
            const float p = a * b;
            const ull qp = pk2(q, p);
#pragma unroll
            for (int j = 0; j < 4; j++) {
                const int k = e - j;              // compile-time
                if (k >= 0 && k < 11) {
                    const int ks = (k < 6) ? k : 10 - k;
                    mAB[j] = fma2(wpk(ks), ab, mAB[j]);
                    mQP[j] = fma2(wpk(ks), qp, mQP[j]);
                }
            }
        }
    }
#pragma unroll
    for (int j = 0; j < 4; j++) {
        const int c = cbase + j;
        sHm[c * HCOL + hr] = mAB[j];
        sHq[c * HCOL + hr] = mQP[j];
    }
}

__global__ __launch_bounds__(NTHREADS, 4)
void ssim_kernel(const float* __restrict__ img1, const float* __restrict__ img2,
                 float* __restrict__ out) {
    extern __shared__ float sm[];
    float2* sAB = reinterpret_cast<float2*>(sm);                 // [74][46]
    ull*    sHm = reinterpret_cast<ull*>(sm + ABFLOATS);         // [32][42]
    ull*    sHq = sHm + HPLANE;                                  // [32][42]
    __shared__ float red[NWARPS];

    const int t    = threadIdx.x;
    const int lane = t & 31;
    const int wid  = t >> 5;        // 0..11
    const int gx0  = blockIdx.x * TW - HALO;
    const int gy0  = blockIdx.y * TH - HALO;
    const float* base1 = img1 + (size_t)blockIdx.z * (IMG * IMG);
    const float* base2 = img2 + (size_t)blockIdx.z * (IMG * IMG);

    // ---- Phase 1: software-pipelined stage of AB (zero-padded) ----
    {
        float a0[7], b0[7], a1[7], b1[7];
        const int gxA = gx0 + lane;
        const int gxB = gx0 + lane + 32;
        const bool okA0 = (unsigned)gxA < (unsigned)IMG;
        const bool okB0 = (lane < 10) && ((unsigned)gxB < (unsigned)IMG);
#pragma unroll
        for (int i = 0; i < 7; i++) {
            const int r  = wid + i * NWARPS;
            const int gy = gy0 + r;
            const bool yok = (r < ROWS) && ((unsigned)gy < (unsigned)IMG);
            const bool okA = yok && okA0;
            const bool okB = yok && okB0;
            const int oA = gy * IMG + gxA;
            const int oB = gy * IMG + gxB;
            a0[i] = okA ? base1[oA] : 0.0f;
            b0[i] = okA ? base2[oA] : 0.0f;
            a1[i] = okB ? base1[oB] : 0.0f;
            b1[i] = okB ? base2[oB] : 0.0f;
        }
#pragma unroll
        for (int i = 0; i < 7; i++) {
            const int r = wid + i * NWARPS;
            if (r < ROWS) {
                sAB[r * ABROW + lane] = make_float2(a0[i], b0[i]);
                if (lane < 10)
                    sAB[r * ABROW + lane + 32] = make_float2(a1[i], b1[i]);
            }
        }
    }
    __syncthreads();

    float lsum = 0.0f;

    // ==== chunk 1: h-rows 0..41, outputs 0..31 ====
    if (t < 8 * 42) {                        // 336 tasks
        const int g = t / 42;                // 0..7
        const int r = t - g * 42;            // 0..41
        p2_task(sAB + r * ABROW + g * 4, sHm, sHq, g * 4, r);
    }
    __syncthreads();
    if (wid < 8) {
        lsum += p3_group4(sHm, sHq, lane * HCOL + 4 * wid);
    }
    __syncthreads();

    // ==== carry copy: H rows 32..41 -> rows 0..9 (both planes) ====
    // 640 ull total; i = k*32 + col, k=0..19 (k<10: Hm row k; else Hq row k-10)
    if (t < 320) {
        const int col = t & 31;
        const int k   = t >> 5;              // 0..9
        sHm[col * HCOL + k] = sHm[col * HCOL + 32 + k];
        sHq[col * HCOL + k] = sHq[col * HCOL + 32 + k];
    }
    __syncthreads();

    // ==== chunk 2: compute only h-rows 42..73 -> H[10..41] ====
    if (t < 256) {                           // shift-only addressing
        const int g = t >> 5;                // 0..7
        const int r = t & 31;                // 0..31
        p2_task(sAB + (42 + r) * ABROW + g * 4, sHm, sHq, g * 4, 10 + r);
    }
    __syncthreads();
    if (wid < 8) {
        lsum += p3_group4(sHm, sHq, lane * HCOL + 4 * wid);
    }

    // ---- warp reduce -> block reduce -> one global atomic per block ----
#pragma unroll
    for (int off = 16; off > 0; off >>= 1)
        lsum += __shfl_xor_sync(0xffffffffu, lsum, off);
    if (lane == 0) red[wid] = lsum;
    __syncthreads();
    if (t == 0) {
        float s = 0.0f;
#pragma unroll
        for (int i = 0; i < NWARPS; i++) s += red[i];
        atomicAdd(&g_acc, (double)s);
        __threadfence();
        const unsigned old = atomicAdd(&g_cnt, 1u);
        if (old == NBLOCKS - 1) {
            const ull raw = atomicExch(reinterpret_cast<ull*>(&g_acc), 0ull);
            out[0] = (float)(__longlong_as_double(raw) * (1.0 / 16777216.0));
            g_cnt = 0u;
        }
    }
}

extern "C" void kernel_launch(void* const* d_in, const int* in_sizes, int n_in,
                              void* d_out, int out_size) {
    const float* img1 = (const float*)d_in[0];
    const float* img2 = (const float*)d_in[1];
    float* out = (float*)d_out;

    cudaFuncSetAttribute(ssim_kernel,
                         cudaFuncAttributeMaxDynamicSharedMemorySize, SMEM_BYTES);

    dim3 grid(IMG / TW, IMG / TH, 64);   // 16 x 8 x 64 = 8192 blocks
    ssim_kernel<<<grid, NTHREADS, SMEM_BYTES>>>(img1, img2, out);
}